// round 3
// baseline (speedup 1.0000x reference)
#include <cuda_runtime.h>

// IntegrableMLP via one forward pass + one VJP (see R0 derivation):
//   forward: z0,a0,d0 ; z1,a1,d1 ; z2,d2
//   backward: u2 = V.*d2 ; u1 = (W2^T u2).*d1 ; u0 = (W1^T u1).*d0 ; out = W0^T u0
// All weight reads are float4 (LDS.128) — the R0 kernel was shared-pipe bound
// on scalar LDS (L1=71%, fma=35%).

#define N0 32
#define N1 32
#define N2 16

__global__ __launch_bounds__(128) void mlp_vjp_kernel(
    const float* __restrict__ inputs,
    const float* __restrict__ W0, const float* __restrict__ b0,
    const float* __restrict__ W1, const float* __restrict__ b1,
    const float* __restrict__ W2, const float* __restrict__ b2,
    const float* __restrict__ V,
    float* __restrict__ out, int B)
{
    __shared__ __align__(16) float sW1 [N1 * N0];   // [out][in], rows contiguous
    __shared__ __align__(16) float sW1T[N0 * N1];   // [in][out]
    __shared__ __align__(16) float sW2 [N2 * N1];   // [16][32]
    __shared__ __align__(16) float sW2T[N1 * N2];   // [32][16]
    __shared__ __align__(16) float sW0 [N0 * 2];    // [32][2]
    __shared__ float sb0[N0], sb1[N1], sb2[N2], sV[N2];

    const int tid = threadIdx.x;
    for (int i = tid; i < N0 * 2; i += blockDim.x) sW0[i] = W0[i];
    for (int i = tid; i < N0; i += blockDim.x)     sb0[i] = b0[i];
    for (int i = tid; i < N1 * N0; i += blockDim.x) {
        float w = W1[i];
        int j = i >> 5, k = i & 31;
        sW1[i] = w;
        sW1T[k * N1 + j] = w;
    }
    for (int i = tid; i < N1; i += blockDim.x)     sb1[i] = b1[i];
    for (int i = tid; i < N2 * N1; i += blockDim.x) {
        float w = W2[i];
        int j = i >> 5, k = i & 31;
        sW2[i] = w;
        sW2T[k * N2 + j] = w;
    }
    for (int i = tid; i < N2; i += blockDim.x) { sb2[i] = b2[i]; sV[i] = V[i]; }
    __syncthreads();

    const int idx = blockIdx.x * blockDim.x + tid;
    if (idx >= B) return;

    const float2 x = reinterpret_cast<const float2*>(inputs)[idx];

    float a[N0], d0[N0], d1[N1], u2[N2];

    // ---- layer 0 ----  (W0 rows are float2; read as float4 = 2 rows)
    {
        const float4* w0v = reinterpret_cast<const float4*>(sW0);
        #pragma unroll
        for (int jj = 0; jj < N0 / 2; jj++) {
            float4 w = w0v[jj];
            int j = 2 * jj;
            float z0 = fmaf(x.y, w.y, fmaf(x.x, w.x, sb0[j]));
            float z1 = fmaf(x.y, w.w, fmaf(x.x, w.z, sb0[j + 1]));
            float s0 = __fdividef(1.0f, 1.0f + __expf(-z0));
            float s1 = __fdividef(1.0f, 1.0f + __expf(-z1));
            float sw0 = z0 * s0, sw1 = z1 * s1;
            a[j] = sw0;      a[j + 1] = sw1;
            d0[j]     = fmaf(s0, 1.0f - sw0, sw0);
            d0[j + 1] = fmaf(s1, 1.0f - sw1, sw1);
        }
    }

    // ---- layer 1 ----
    float anew[N1];
    #pragma unroll
    for (int j = 0; j < N1; j++) {
        const float4* row = reinterpret_cast<const float4*>(sW1 + j * N0);
        float z = sb1[j];
        #pragma unroll
        for (int k = 0; k < N0 / 4; k++) {
            float4 w = row[k];
            z = fmaf(a[4 * k],     w.x, z);
            z = fmaf(a[4 * k + 1], w.y, z);
            z = fmaf(a[4 * k + 2], w.z, z);
            z = fmaf(a[4 * k + 3], w.w, z);
        }
        float s = __fdividef(1.0f, 1.0f + __expf(-z));
        float sw = z * s;
        anew[j] = sw;
        d1[j] = fmaf(s, 1.0f - sw, sw);
    }

    // ---- layer 2 (fold V into u2 immediately) ----
    #pragma unroll
    for (int j = 0; j < N2; j++) {
        const float4* row = reinterpret_cast<const float4*>(sW2 + j * N1);
        float z = sb2[j];
        #pragma unroll
        for (int k = 0; k < N1 / 4; k++) {
            float4 w = row[k];
            z = fmaf(anew[4 * k],     w.x, z);
            z = fmaf(anew[4 * k + 1], w.y, z);
            z = fmaf(anew[4 * k + 2], w.z, z);
            z = fmaf(anew[4 * k + 3], w.w, z);
        }
        float s = __fdividef(1.0f, 1.0f + __expf(-z));
        float sw = z * s;
        u2[j] = sV[j] * fmaf(s, 1.0f - sw, sw);
    }

    // ---- backward: u1 = (W2^T u2) .* d1 ----
    float u1[N1];
    #pragma unroll
    for (int k = 0; k < N1; k++) {
        const float4* col = reinterpret_cast<const float4*>(sW2T + k * N2);
        float acc = 0.0f;
        #pragma unroll
        for (int j = 0; j < N2 / 4; j++) {
            float4 w = col[j];
            acc = fmaf(u2[4 * j],     w.x, acc);
            acc = fmaf(u2[4 * j + 1], w.y, acc);
            acc = fmaf(u2[4 * j + 2], w.z, acc);
            acc = fmaf(u2[4 * j + 3], w.w, acc);
        }
        u1[k] = acc * d1[k];
    }

    // ---- backward: u0 = (W1^T u1) .* d0 ----
    float u0[N0];
    #pragma unroll
    for (int k = 0; k < N0; k++) {
        const float4* col = reinterpret_cast<const float4*>(sW1T + k * N1);
        float acc = 0.0f;
        #pragma unroll
        for (int j = 0; j < N1 / 4; j++) {
            float4 w = col[j];
            acc = fmaf(u1[4 * j],     w.x, acc);
            acc = fmaf(u1[4 * j + 1], w.y, acc);
            acc = fmaf(u1[4 * j + 2], w.z, acc);
            acc = fmaf(u1[4 * j + 3], w.w, acc);
        }
        u0[k] = acc * d0[k];
    }

    // ---- out[:,n] = W0^T u0 ----  (float4 = 2 rows of W0)
    float o0 = 0.0f, o1 = 0.0f;
    {
        const float4* w0v = reinterpret_cast<const float4*>(sW0);
        #pragma unroll
        for (int jj = 0; jj < N0 / 2; jj++) {
            float4 w = w0v[jj];
            o0 = fmaf(u0[2 * jj],     w.x, o0);
            o1 = fmaf(u0[2 * jj],     w.y, o1);
            o0 = fmaf(u0[2 * jj + 1], w.z, o0);
            o1 = fmaf(u0[2 * jj + 1], w.w, o1);
        }
    }

    reinterpret_cast<float2*>(out)[idx] = make_float2(o0, o1);
}

extern "C" void kernel_launch(void* const* d_in, const int* in_sizes, int n_in,
                              void* d_out, int out_size)
{
    const float* inputs = (const float*)d_in[0];
    const float* W0 = (const float*)d_in[1];
    const float* b0 = (const float*)d_in[2];
    const float* W1 = (const float*)d_in[3];
    const float* b1 = (const float*)d_in[4];
    const float* W2 = (const float*)d_in[5];
    const float* b2 = (const float*)d_in[6];
    const float* V  = (const float*)d_in[7];
    float* out = (float*)d_out;

    const int B = in_sizes[0] / 2;      // inputs is [B, 2]
    const int threads = 128;
    const int blocks = (B + threads - 1) / threads;
    mlp_vjp_kernel<<<blocks, threads>>>(inputs, W0, b0, W1, b1, W2, b2, V, out, B);
}